// round 4
// baseline (speedup 1.0000x reference)
#include <cuda_runtime.h>
#include <cstdint>

#define DE 128
#define BMAX 8192
#define NMAX 1000000
#define CAP 192      // rows cached in SMEM per buffer (segment mean 122, max ~170)
#define SCAP2 384    // max segment size for score array (clamp; statistically unreachable)
#define CH 4         // segments per work-steal grab

__device__ float g_qW[BMAX * DE];
__device__ int   g_hist[BMAX];
__device__ int   g_off[BMAX];
__device__ int   g_cur[BMAX];
__device__ int   g_nodes[NMAX];
__device__ int   g_work;

__device__ __forceinline__ uint32_t smem_u32(const void* p) {
    uint32_t a;
    asm("{ .reg .u64 t; cvta.to.shared.u64 t, %1; cvt.u32.u64 %0, t; }" : "=r"(a) : "l"(p));
    return a;
}

// ---------------------------------------------------------------- qW = query @ W  (+ zero hist & work counter)
__global__ void k_qw(const float* __restrict__ query, const float* __restrict__ W, int B) {
    int gidx = blockIdx.x * blockDim.x + threadIdx.x;
    if (gidx < B) g_hist[gidx] = 0;
    if (gidx == 0) g_work = 0;

    __shared__ float qs[32][DE + 4];
    int row0 = blockIdx.x * 32;
    int t = threadIdx.x;  // 0..127
    #pragma unroll
    for (int j = 0; j < 32; j++) {
        int r = row0 + j;
        qs[j][t] = (r < B) ? query[r * DE + t] : 0.f;
    }
    __syncthreads();
    float acc[32];
    #pragma unroll
    for (int r = 0; r < 32; r++) acc[r] = 0.f;
    for (int k = 0; k < DE; k++) {
        float w = W[k * DE + t];
        #pragma unroll
        for (int r = 0; r < 32; r++) acc[r] = fmaf(qs[r][k], w, acc[r]);
    }
    #pragma unroll
    for (int r = 0; r < 32; r++) {
        int rr = row0 + r;
        if (rr < B) g_qW[rr * DE + t] = acc[r];
    }
}

// ---------------------------------------------------------------- histogram of index (int4 loads)
__global__ void k_hist(const int* __restrict__ index, int N) {
    int i = blockIdx.x * blockDim.x + threadIdx.x;
    int i4 = i * 4;
    if (i4 + 3 < N) {
        int4 v = *(const int4*)(index + i4);
        atomicAdd(&g_hist[v.x], 1);
        atomicAdd(&g_hist[v.y], 1);
        atomicAdd(&g_hist[v.z], 1);
        atomicAdd(&g_hist[v.w], 1);
    } else {
        for (int j = i4; j < N; j++) atomicAdd(&g_hist[index[j]], 1);
    }
}

// ---------------------------------------------------------------- exclusive scan (256 thr x 32 bins)
__global__ void k_scan(int B) {
    __shared__ int warp_sums[8];
    int t = threadIdx.x;
    int lane = t & 31, w = t >> 5;
    int base = t * 32;
    int loc[32];
    int s = 0;
    const int4* hp = (const int4*)&g_hist[base];
    #pragma unroll
    for (int j = 0; j < 8; j++) {
        int4 v = (base + j * 4 + 3 < B) ? hp[j] : make_int4(0, 0, 0, 0);
        loc[j * 4 + 0] = s; s += v.x;
        loc[j * 4 + 1] = s; s += v.y;
        loc[j * 4 + 2] = s; s += v.z;
        loc[j * 4 + 3] = s; s += v.w;
    }
    int incl = s;
    #pragma unroll
    for (int o = 1; o < 32; o <<= 1) {
        int v = __shfl_up_sync(0xffffffffu, incl, o);
        if (lane >= o) incl += v;
    }
    if (lane == 31) warp_sums[w] = incl;
    __syncthreads();
    int wpre = 0;
    #pragma unroll
    for (int k = 0; k < 8; k++) wpre += (k < w) ? warp_sums[k] : 0;
    int pre = wpre + incl - s;
    int4* op = (int4*)&g_off[base];
    int4* cp = (int4*)&g_cur[base];
    #pragma unroll
    for (int j = 0; j < 8; j++) {
        if (base + j * 4 + 3 < B) {
            int4 o4 = make_int4(pre + loc[j * 4 + 0], pre + loc[j * 4 + 1],
                                pre + loc[j * 4 + 2], pre + loc[j * 4 + 3]);
            op[j] = o4;
            cp[j] = o4;
        }
    }
}

// ---------------------------------------------------------------- scatter node ids into CSR
__global__ void k_scatter(const int* __restrict__ index, int N) {
    int i = blockIdx.x * blockDim.x + threadIdx.x;
    if (i < N) {
        int b = index[i];
        int p = atomicAdd(&g_cur[b], 1);
        g_nodes[p] = i;
    }
}

// ---------------------------------------------------------------- persistent double-buffered main
// SMEM: rows[2][CAP*DE] | sv[2][SCAP2] | red[64] | part[512] | shi[4]
#define SMEM_FLOATS (2 * CAP * DE + 2 * SCAP2 + 64 + 512 + 4)
#define SMEM_BYTES  (SMEM_FLOATS * 4)

__global__ void __launch_bounds__(512, 1) k_main(const float* __restrict__ values,
                                                 float* __restrict__ out, int B) {
    extern __shared__ float smem[];
    float* rows = smem;                     // [2][CAP*DE]
    float* sv   = rows + 2 * CAP * DE;      // [2][SCAP2]
    float* red  = sv + 2 * SCAP2;           // [64]
    float* part = red + 64;                 // [512]
    int*   shi  = (int*)(part + 512);       // [4]

    int tid = threadIdx.x, lane = tid & 31, wid = tid >> 5;

    // issue all cached-row loads for one segment into a buffer (warp-per-row, batch 4)
    auto issue_rows = [&](int bufi, int off, int capn) {
        float* rb = rows + bufi * CAP * DE;
        for (int i = wid; i < capn; i += 64) {
            int nd[4];
            #pragma unroll
            for (int u = 0; u < 4; u++) {
                int ii = i + u * 16;
                nd[u] = (ii < capn) ? __ldg(&g_nodes[off + ii]) : 0;
            }
            #pragma unroll
            for (int u = 0; u < 4; u++) {
                int ii = i + u * 16;
                if (ii < capn) {
                    const float* gp = values + (size_t)nd[u] * DE + lane * 4;
                    uint32_t sa = smem_u32(rb + ii * DE + lane * 4);
                    asm volatile("cp.async.cg.shared.global [%0], [%1], 16;" :: "r"(sa), "l"(gp));
                }
            }
        }
    };

    // grab first chunk
    if (tid == 0) shi[0] = atomicAdd(&g_work, CH);
    __syncthreads();
    int my = shi[0];
    int chunk_end = my + CH;
    int cur = 0;
    int off_c = 0, cnt_c = 0;
    if (my < B) {
        off_c = __ldg(&g_off[my]);
        cnt_c = __ldg(&g_hist[my]);
        if (cnt_c > SCAP2) cnt_c = SCAP2;
        issue_rows(0, off_c, (cnt_c < CAP) ? cnt_c : CAP);
    }
    asm volatile("cp.async.commit_group;" ::: "memory");

    while (my < B) {
        // -------- determine & prefetch next segment
        bool last = (my + 1 >= chunk_end);
        if (tid == 0 && last) shi[1] = atomicAdd(&g_work, CH);
        __syncthreads();
        int nxt, nchunk_end = chunk_end;
        if (last) { nxt = shi[1]; nchunk_end = nxt + CH; }
        else nxt = my + 1;
        if (nxt >= B) nxt = B;

        int off_n = 0, cnt_n = 0;
        if (nxt < B) {
            off_n = __ldg(&g_off[nxt]);
            cnt_n = __ldg(&g_hist[nxt]);
            if (cnt_n > SCAP2) cnt_n = SCAP2;
            issue_rows(cur ^ 1, off_n, (cnt_n < CAP) ? cnt_n : CAP);
        }
        asm volatile("cp.async.commit_group;" ::: "memory");
        asm volatile("cp.async.wait_group 1;" ::: "memory");   // current buffer ready
        __syncthreads();

        // -------- compute on buffer `cur` for segment `my`
        float* rb  = rows + cur * CAP * DE;
        float* svb = sv + cur * SCAP2;
        float4 qv = *(const float4*)(g_qW + (size_t)my * DE + lane * 4);

        for (int i = wid; i < cnt_c; i += 16) {
            float4 v;
            if (i < CAP) v = *(float4*)(rb + i * DE + lane * 4);
            else {
                int nd = __ldg(&g_nodes[off_c + i]);
                v = *(const float4*)(values + (size_t)nd * DE + lane * 4);
            }
            float d = v.x * qv.x + v.y * qv.y + v.z * qv.z + v.w * qv.w;
            #pragma unroll
            for (int o = 16; o > 0; o >>= 1) d += __shfl_down_sync(0xffffffffu, d, o);
            if (lane == 0) svb[i] = d * 0.08838834764831845f;   // 1/sqrt(128)
        }
        __syncthreads();

        // max
        float m = -3.4e38f;
        for (int i = tid; i < cnt_c; i += 512) m = fmaxf(m, svb[i]);
        #pragma unroll
        for (int o = 16; o > 0; o >>= 1) m = fmaxf(m, __shfl_xor_sync(0xffffffffu, m, o));
        if (lane == 0) red[wid] = m;
        __syncthreads();
        if (tid == 0) {
            float mm = red[0];
            #pragma unroll
            for (int w = 1; w < 16; w++) mm = fmaxf(mm, red[w]);
            red[16] = mm;
        }
        __syncthreads();
        float smax = red[16];

        // exp + sum
        float ss = 0.f;
        for (int i = tid; i < cnt_c; i += 512) {
            float e = __expf(svb[i] - smax);
            svb[i] = e;
            ss += e;
        }
        #pragma unroll
        for (int o = 16; o > 0; o >>= 1) ss += __shfl_xor_sync(0xffffffffu, ss, o);
        if (lane == 0) red[32 + wid] = ss;
        __syncthreads();
        if (tid == 0) {
            float s = 0.f;
            #pragma unroll
            for (int w = 0; w < 16; w++) s += red[32 + w];
            red[17] = (s > 0.f) ? 1.f / s : 0.f;
        }
        __syncthreads();
        float inv = red[17];

        // pooling: 4 groups of 128 threads
        int g = tid >> 7, d = tid & 127;
        float acc = 0.f;
        for (int i = g; i < cnt_c; i += 4) {
            float w = svb[i];
            float v = (i < CAP) ? rb[i * DE + d]
                                : values[(size_t)__ldg(&g_nodes[off_c + i]) * DE + d];
            acc = fmaf(w, v, acc);
        }
        part[tid] = acc * inv;
        __syncthreads();
        if (tid < DE)
            out[(size_t)my * DE + tid] =
                part[tid] + part[tid + 128] + part[tid + 256] + part[tid + 384];

        // -------- advance (no extra sync needed: next-iter top sync precedes buffer overwrite)
        my = nxt;
        chunk_end = nchunk_end;
        off_c = off_n;
        cnt_c = cnt_n;
        cur ^= 1;
    }
}

// ---------------------------------------------------------------- launch
extern "C" void kernel_launch(void* const* d_in, const int* in_sizes, int n_in,
                              void* d_out, int out_size) {
    const float* query  = (const float*)d_in[0];
    const float* values = (const float*)d_in[1];
    const int*   index  = (const int*)d_in[2];
    const float* W      = (const float*)d_in[3];
    float* out = (float*)d_out;

    int B = in_sizes[0] / DE;   // 8192
    int N = in_sizes[2];        // 1,000,000

    cudaFuncSetAttribute(k_main, cudaFuncAttributeMaxDynamicSharedMemorySize, SMEM_BYTES);

    k_qw<<<(B + 31) / 32, 128>>>(query, W, B);
    k_hist<<<(N / 4 + 255) / 256, 256>>>(index, N);
    k_scan<<<1, 256>>>(B);
    k_scatter<<<(N + 255) / 256, 256>>>(index, N);
    k_main<<<192, 512, SMEM_BYTES>>>(values, out, B);
}

// round 5
// speedup vs baseline: 1.9757x; 1.9757x over previous
#include <cuda_runtime.h>
#include <cstdint>

#define DE 128
#define BMAX 8192
#define NMAX 1000000
#define SCAP 512     // max segment size (mean 122, sigma ~11; P(>512) ~ 0)

__device__ float g_qW[BMAX * DE];
__device__ int   g_hist[BMAX];
__device__ int   g_off[BMAX];
__device__ int   g_cur[BMAX];
__device__ int   g_nodes[NMAX];

// ---------------------------------------------------------------- qW = query @ W  (+ zero hist)
__global__ void k_qw(const float* __restrict__ query, const float* __restrict__ W, int B) {
    int gidx = blockIdx.x * blockDim.x + threadIdx.x;
    if (gidx < B) g_hist[gidx] = 0;

    __shared__ float qs[32][DE + 4];
    int row0 = blockIdx.x * 32;
    int t = threadIdx.x;  // 0..127
    #pragma unroll
    for (int j = 0; j < 32; j++) {
        int r = row0 + j;
        qs[j][t] = (r < B) ? query[r * DE + t] : 0.f;
    }
    __syncthreads();
    float acc[32];
    #pragma unroll
    for (int r = 0; r < 32; r++) acc[r] = 0.f;
    for (int k = 0; k < DE; k++) {
        float w = W[k * DE + t];
        #pragma unroll
        for (int r = 0; r < 32; r++) acc[r] = fmaf(qs[r][k], w, acc[r]);
    }
    #pragma unroll
    for (int r = 0; r < 32; r++) {
        int rr = row0 + r;
        if (rr < B) g_qW[rr * DE + t] = acc[r];
    }
}

// ---------------------------------------------------------------- histogram of index (int4 loads)
__global__ void k_hist(const int* __restrict__ index, int N) {
    int i = blockIdx.x * blockDim.x + threadIdx.x;
    int i4 = i * 4;
    if (i4 + 3 < N) {
        int4 v = *(const int4*)(index + i4);
        atomicAdd(&g_hist[v.x], 1);
        atomicAdd(&g_hist[v.y], 1);
        atomicAdd(&g_hist[v.z], 1);
        atomicAdd(&g_hist[v.w], 1);
    } else {
        for (int j = i4; j < N; j++) atomicAdd(&g_hist[index[j]], 1);
    }
}

// ---------------------------------------------------------------- exclusive scan (256 thr x 32 bins)
__global__ void k_scan(int B) {
    __shared__ int warp_sums[8];
    int t = threadIdx.x;
    int lane = t & 31, w = t >> 5;
    int base = t * 32;
    int loc[32];
    int s = 0;
    const int4* hp = (const int4*)&g_hist[base];
    #pragma unroll
    for (int j = 0; j < 8; j++) {
        int4 v = (base + j * 4 + 3 < B) ? hp[j] : make_int4(0, 0, 0, 0);
        loc[j * 4 + 0] = s; s += v.x;
        loc[j * 4 + 1] = s; s += v.y;
        loc[j * 4 + 2] = s; s += v.z;
        loc[j * 4 + 3] = s; s += v.w;
    }
    int incl = s;
    #pragma unroll
    for (int o = 1; o < 32; o <<= 1) {
        int v = __shfl_up_sync(0xffffffffu, incl, o);
        if (lane >= o) incl += v;
    }
    if (lane == 31) warp_sums[w] = incl;
    __syncthreads();
    int wpre = 0;
    #pragma unroll
    for (int k = 0; k < 8; k++) wpre += (k < w) ? warp_sums[k] : 0;
    int pre = wpre + incl - s;
    int4* op = (int4*)&g_off[base];
    int4* cp = (int4*)&g_cur[base];
    #pragma unroll
    for (int j = 0; j < 8; j++) {
        if (base + j * 4 + 3 < B) {
            int4 o4 = make_int4(pre + loc[j * 4 + 0], pre + loc[j * 4 + 1],
                                pre + loc[j * 4 + 2], pre + loc[j * 4 + 3]);
            op[j] = o4;
            cp[j] = o4;
        }
    }
}

// ---------------------------------------------------------------- scatter node ids into CSR (x4 for MLP)
__global__ void k_scatter(const int* __restrict__ index, int N) {
    int i = blockIdx.x * blockDim.x + threadIdx.x;
    int i4 = i * 4;
    if (i4 + 3 < N) {
        int4 v = *(const int4*)(index + i4);
        int p0 = atomicAdd(&g_cur[v.x], 1);
        int p1 = atomicAdd(&g_cur[v.y], 1);
        int p2 = atomicAdd(&g_cur[v.z], 1);
        int p3 = atomicAdd(&g_cur[v.w], 1);
        g_nodes[p0] = i4;
        g_nodes[p1] = i4 + 1;
        g_nodes[p2] = i4 + 2;
        g_nodes[p3] = i4 + 3;
    } else {
        for (int j = i4; j < N; j++) {
            int p = atomicAdd(&g_cur[index[j]], 1);
            g_nodes[p] = j;
        }
    }
}

// ---------------------------------------------------------------- main: block per segment, NO row cache
// Scoring reads rows from DRAM; pooling re-reads them ~2-5K cycles later -> L2 hits.
// Tiny smem => 8 blocks/SM => 64 warps of latency hiding.
__global__ void __launch_bounds__(256) k_main(const float* __restrict__ values,
                                              float* __restrict__ out, int B) {
    __shared__ float sv[SCAP];
    __shared__ int   nds[SCAP];
    __shared__ float qw[DE];
    __shared__ float red[64];
    __shared__ float part[256];

    int b = blockIdx.x;
    int tid = threadIdx.x, lane = tid & 31, wid = tid >> 5;

    int off = g_off[b];
    int cnt = g_hist[b];
    if (cnt > SCAP) cnt = SCAP;  // statistically unreachable

    if (tid < DE) qw[tid] = g_qW[(size_t)b * DE + tid];
    for (int i = tid; i < cnt; i += 256) nds[i] = g_nodes[off + i];
    __syncthreads();

    float4 qv = *(float4*)&qw[lane * 4];

    // -------- Phase A: scoring, warp per row, 4 rows in flight per warp
    for (int i0 = wid * 4; i0 < cnt; i0 += 32) {
        float4 v[4];
        #pragma unroll
        for (int u = 0; u < 4; u++) {
            int ii = i0 + u;
            if (ii < cnt)
                v[u] = __ldg((const float4*)(values + (size_t)nds[ii] * DE + lane * 4));
        }
        float d[4];
        #pragma unroll
        for (int u = 0; u < 4; u++)
            d[u] = v[u].x * qv.x + v[u].y * qv.y + v[u].z * qv.z + v[u].w * qv.w;
        #pragma unroll
        for (int o = 16; o > 0; o >>= 1) {
            #pragma unroll
            for (int u = 0; u < 4; u++)
                d[u] += __shfl_down_sync(0xffffffffu, d[u], o);
        }
        if (lane == 0) {
            #pragma unroll
            for (int u = 0; u < 4; u++)
                if (i0 + u < cnt) sv[i0 + u] = d[u] * 0.08838834764831845f;  // 1/sqrt(128)
        }
    }
    __syncthreads();

    // -------- max reduce
    float m = -3.4e38f;
    for (int i = tid; i < cnt; i += 256) m = fmaxf(m, sv[i]);
    #pragma unroll
    for (int o = 16; o > 0; o >>= 1) m = fmaxf(m, __shfl_xor_sync(0xffffffffu, m, o));
    if (lane == 0) red[wid] = m;
    __syncthreads();
    if (tid == 0) {
        float mm = red[0];
        #pragma unroll
        for (int w = 1; w < 8; w++) mm = fmaxf(mm, red[w]);
        red[8] = mm;
    }
    __syncthreads();
    float smax = red[8];

    // -------- exp + sum
    float ss = 0.f;
    for (int i = tid; i < cnt; i += 256) {
        float e = __expf(sv[i] - smax);
        sv[i] = e;
        ss += e;
    }
    #pragma unroll
    for (int o = 16; o > 0; o >>= 1) ss += __shfl_xor_sync(0xffffffffu, ss, o);
    if (lane == 0) red[16 + wid] = ss;
    __syncthreads();
    if (tid == 0) {
        float s = 0.f;
        #pragma unroll
        for (int w = 0; w < 8; w++) s += red[16 + w];
        red[9] = (s > 0.f) ? 1.f / s : 0.f;
    }
    __syncthreads();
    float inv = red[9];

    // -------- Phase B: pooling, 2 groups of 128 threads, 4 rows in flight each
    int g = tid >> 7, d = tid & 127;
    float a0 = 0.f, a1 = 0.f, a2 = 0.f, a3 = 0.f;
    for (int i0 = g * 4; i0 < cnt; i0 += 8) {
        float v0 = 0.f, v1 = 0.f, v2 = 0.f, v3 = 0.f;
        float w0 = 0.f, w1 = 0.f, w2 = 0.f, w3 = 0.f;
        if (i0 + 0 < cnt) { v0 = __ldg(values + (size_t)nds[i0 + 0] * DE + d); w0 = sv[i0 + 0]; }
        if (i0 + 1 < cnt) { v1 = __ldg(values + (size_t)nds[i0 + 1] * DE + d); w1 = sv[i0 + 1]; }
        if (i0 + 2 < cnt) { v2 = __ldg(values + (size_t)nds[i0 + 2] * DE + d); w2 = sv[i0 + 2]; }
        if (i0 + 3 < cnt) { v3 = __ldg(values + (size_t)nds[i0 + 3] * DE + d); w3 = sv[i0 + 3]; }
        a0 = fmaf(w0, v0, a0);
        a1 = fmaf(w1, v1, a1);
        a2 = fmaf(w2, v2, a2);
        a3 = fmaf(w3, v3, a3);
    }
    part[tid] = ((a0 + a1) + (a2 + a3)) * inv;
    __syncthreads();
    if (tid < DE) out[(size_t)b * DE + tid] = part[tid] + part[tid + DE];
}

// ---------------------------------------------------------------- launch
extern "C" void kernel_launch(void* const* d_in, const int* in_sizes, int n_in,
                              void* d_out, int out_size) {
    const float* query  = (const float*)d_in[0];
    const float* values = (const float*)d_in[1];
    const int*   index  = (const int*)d_in[2];
    const float* W      = (const float*)d_in[3];
    float* out = (float*)d_out;

    int B = in_sizes[0] / DE;   // 8192
    int N = in_sizes[2];        // 1,000,000

    k_qw<<<(B + 31) / 32, 128>>>(query, W, B);
    k_hist<<<(N / 4 + 255) / 256, 256>>>(index, N);
    k_scan<<<1, 256>>>(B);
    k_scatter<<<(N / 4 + 255) / 256, 256>>>(index, N);
    k_main<<<B, 256>>>(values, out, B);
}